// round 14
// baseline (speedup 1.0000x reference)
#include <cuda_runtime.h>
#include <cuda_fp16.h>
#include <cstdint>

#define BB 2
#define KK 512
#define QQ 512
#define TT 128
#define NREP 16

// ---------------- device scratch ----------------
__device__ float g_k[BB * KK * TT];
__device__ float g_q[BB * QQ * TT];
__device__ float g_v[BB * KK * TT];
__device__ float g_w[BB * KK * TT];                  // per (b,k,u) scale v_u/(T+e^m)
__device__ float g_accr[NREP * BB * QQ * TT];        // k-split partial sums
__device__ __half g_xe[(size_t)BB * KK * TT * QQ];   // 128MB unscaled y = x*e^x
__device__ unsigned char g_ak[(size_t)BB * KK * 32768];  // 32MB swizzled fp16 Wl*k images
__device__ unsigned char g_qh[BB * 4 * 32768];           // 256KB swizzled fp16 q tiles

// ---------------- helpers ----------------
__device__ __forceinline__ uint32_t smem_u32(const void* p) {
    uint32_t a;
    asm("{ .reg .u64 t; cvta.to.shared.u64 t, %1; cvt.u32.u64 %0, t; }" : "=r"(a) : "l"(p));
    return a;
}
__device__ __forceinline__ void ldsm_x4(uint32_t& r0, uint32_t& r1, uint32_t& r2, uint32_t& r3,
                                        uint32_t addr) {
    asm volatile("ldmatrix.sync.aligned.m8n8.x4.shared.b16 {%0,%1,%2,%3}, [%4];"
                 : "=r"(r0), "=r"(r1), "=r"(r2), "=r"(r3) : "r"(addr));
}
__device__ __forceinline__ void mma16816(float& d0, float& d1, float& d2, float& d3,
                                         uint32_t a0, uint32_t a1, uint32_t a2, uint32_t a3,
                                         uint32_t b0, uint32_t b1) {
    asm volatile("mma.sync.aligned.m16n8k16.row.col.f32.f16.f16.f32 "
                 "{%0,%1,%2,%3}, {%4,%5,%6,%7}, {%8,%9}, {%0,%1,%2,%3};"
                 : "+f"(d0), "+f"(d1), "+f"(d2), "+f"(d3)
                 : "r"(a0), "r"(a1), "r"(a2), "r"(a3), "r"(b0), "r"(b1));
}
__device__ __forceinline__ void cp16(uint32_t smem, const void* g) {
    asm volatile("cp.async.cg.shared.global [%0], [%1], 16;" :: "r"(smem), "l"(g));
}
#define CP_COMMIT() asm volatile("cp.async.commit_group;" ::: "memory")
#define CP_WAIT(N)  asm volatile("cp.async.wait_group %0;" :: "n"(N) : "memory")

// smem byte layout for pass1 (total 99328 -> 2 CTAs/SM)
#define A_OFF    0          // 32KB: A_k image; reused as y staging after frag load
#define X0_OFF   32768      // 32KB X buffer 0
#define X1_OFF   65536      // 32KB X buffer 1
#define STAT_OFF 98304      // m[128], T[128] = 1KB
#define P1_SMEM  99328

// ---------------- prep: build swizzled fp16 images ----------------
__global__ __launch_bounds__(256) void prep_images(const float* __restrict__ Wl) {
    int blk = blockIdx.x;
    int tid = threadIdx.x;
    int r = tid >> 1, h = tid & 1;
    int r7 = r & 7;
    if (blk < BB * KK) {
        int b = blk >> 9, k = blk & 511;
        const float4* wrow = (const float4*)(Wl + (size_t)r * TT + h * 64);
        const float4* krow = (const float4*)(g_k + ((size_t)b * KK + k) * TT + h * 64);
        unsigned char* arow = g_ak + (size_t)blk * 32768 + r * 256;
#pragma unroll
        for (int c8 = 0; c8 < 8; c8++) {
            float4 qa = wrow[c8 * 2], qb = wrow[c8 * 2 + 1];
            float4 ka = krow[c8 * 2], kb = krow[c8 * 2 + 1];
            __half2 h0 = __floats2half2_rn(qa.x * ka.x, qa.y * ka.y);
            __half2 h1 = __floats2half2_rn(qa.z * ka.z, qa.w * ka.w);
            __half2 h2 = __floats2half2_rn(qb.x * kb.x, qb.y * kb.y);
            __half2 h3 = __floats2half2_rn(qb.z * kb.z, qb.w * kb.w);
            int chunk = h * 8 + c8;
            uint4 pk;
            pk.x = *(uint32_t*)&h0; pk.y = *(uint32_t*)&h1;
            pk.z = *(uint32_t*)&h2; pk.w = *(uint32_t*)&h3;
            *(uint4*)(arow + ((chunk ^ r7) << 4)) = pk;
        }
    } else {
        int i = blk - BB * KK;            // 0..7: b = i>>2, qt = i&3
        int b = i >> 2, qt = i & 3;
        const float4* qrow = (const float4*)(g_q + ((size_t)b * QQ + qt * 128 + r) * TT + h * 64);
        unsigned char* xrow = g_qh + (size_t)i * 32768 + r * 256;
#pragma unroll
        for (int c8 = 0; c8 < 8; c8++) {
            float4 qa = qrow[c8 * 2], qb = qrow[c8 * 2 + 1];
            __half2 h0 = __floats2half2_rn(qa.x, qa.y);
            __half2 h1 = __floats2half2_rn(qa.z, qa.w);
            __half2 h2 = __floats2half2_rn(qb.x, qb.y);
            __half2 h3 = __floats2half2_rn(qb.z, qb.w);
            int chunk = h * 8 + c8;
            uint4 pk;
            pk.x = *(uint32_t*)&h0; pk.y = *(uint32_t*)&h1;
            pk.z = *(uint32_t*)&h2; pk.w = *(uint32_t*)&h3;
            *(uint4*)(xrow + ((chunk ^ r7) << 4)) = pk;
        }
    }
}

// ---------------- fp32 GEMM 32-row tiles: out[r,u] = sum_t in[r,t]*W[u,t] ----------------
__device__ __forceinline__ void gemm32_body(const float* __restrict__ in,
                                            const float* __restrict__ W,
                                            float* __restrict__ out, int r0) {
    extern __shared__ float smf[];
    float* sW = smf;                 // [128][132]
    float* sI = smf + 128 * 132;     // [32][132]
    int tid = threadIdx.x;
    for (int i = tid; i < 128 * 128; i += 256) { int u = i >> 7, t = i & 127; sW[u * 132 + t] = W[i]; }
    for (int i = tid; i < 32 * 128;  i += 256) {
        int r = i >> 7, t = i & 127;
        sI[r * 132 + t] = in[(size_t)r0 * 128 + i];
    }
    __syncthreads();
    int tx = tid & 15, ty = tid >> 4;
    float acc[2][8];
#pragma unroll
    for (int i = 0; i < 2; i++)
#pragma unroll
        for (int j = 0; j < 8; j++) acc[i][j] = 0.0f;
    for (int t = 0; t < 128; t += 4) {
        float4 a0 = *(const float4*)&sI[(ty * 2 + 0) * 132 + t];
        float4 a1 = *(const float4*)&sI[(ty * 2 + 1) * 132 + t];
#pragma unroll
        for (int j = 0; j < 8; j++) {
            float4 bv = *(const float4*)&sW[(tx + 16 * j) * 132 + t];
            acc[0][j] = fmaf(a0.x, bv.x, acc[0][j]); acc[0][j] = fmaf(a0.y, bv.y, acc[0][j]);
            acc[0][j] = fmaf(a0.z, bv.z, acc[0][j]); acc[0][j] = fmaf(a0.w, bv.w, acc[0][j]);
            acc[1][j] = fmaf(a1.x, bv.x, acc[1][j]); acc[1][j] = fmaf(a1.y, bv.y, acc[1][j]);
            acc[1][j] = fmaf(a1.z, bv.z, acc[1][j]); acc[1][j] = fmaf(a1.w, bv.w, acc[1][j]);
        }
    }
#pragma unroll
    for (int i = 0; i < 2; i++)
#pragma unroll
        for (int j = 0; j < 8; j++)
            out[(size_t)(r0 + ty * 2 + i) * 128 + tx + 16 * j] = acc[i][j];
}

// ---------------- gemm_out: 16-row tiles, folds NREP replica sum ----------------
#define SMEM_GO ((128 * 132 + 16 * 132) * 4)
__global__ __launch_bounds__(256) void gemm_out(const float* __restrict__ W,
                                                float* __restrict__ out) {
    extern __shared__ float smf[];
    float* sW = smf;                 // [128][132]
    float* sI = smf + 128 * 132;     // [16][132]
    int tid = threadIdx.x;
    int r0 = blockIdx.x * 16;
    for (int i = tid; i < 128 * 128; i += 256) { int u = i >> 7, t = i & 127; sW[u * 132 + t] = W[i]; }
    for (int i = tid; i < 16 * 128; i += 256) {
        int r = i >> 7, t = i & 127;
        const size_t off = (size_t)r0 * 128 + i;
        const size_t st = (size_t)BB * QQ * TT;
        float v = 0.0f;
#pragma unroll
        for (int rr = 0; rr < NREP; rr++) v += g_accr[off + (size_t)rr * st];
        sI[r * 132 + t] = v;
    }
    __syncthreads();
    int tx = tid & 15, ty = tid >> 4;   // r = r0+ty, u = tx + 16*j
    float acc[8];
#pragma unroll
    for (int j = 0; j < 8; j++) acc[j] = 0.0f;
    for (int t = 0; t < 128; t += 4) {
        float4 a0 = *(const float4*)&sI[ty * 132 + t];
#pragma unroll
        for (int j = 0; j < 8; j++) {
            float4 bv = *(const float4*)&sW[(tx + 16 * j) * 132 + t];
            acc[j] = fmaf(a0.x, bv.x, acc[j]); acc[j] = fmaf(a0.y, bv.y, acc[j]);
            acc[j] = fmaf(a0.z, bv.z, acc[j]); acc[j] = fmaf(a0.w, bv.w, acc[j]);
        }
    }
#pragma unroll
    for (int j = 0; j < 8; j++)
        out[(size_t)(r0 + ty) * 128 + tx + 16 * j] = acc[j];
}

__global__ __launch_bounds__(256) void proj3(const float* __restrict__ qi, const float* __restrict__ Wq,
                                             const float* __restrict__ ki, const float* __restrict__ Wk,
                                             const float* __restrict__ vi, const float* __restrict__ Wv) {
    int r0 = blockIdx.x * 32;
    if (blockIdx.y == 0)      gemm32_body(qi, Wq, g_q, r0);
    else if (blockIdx.y == 1) gemm32_body(ki, Wk, g_k, r0);
    else                      gemm32_body(vi, Wv, g_v, r0);
}

// load B-fragments for one nt row-block
#define LOAD_BF(dst, ntv)                                                      \
    do {                                                                       \
        int row_ = (ntv) * 8 + brow7;                                          \
        uint32_t rb_ = xb + row_ * 256;                                        \
        int r7_ = row_ & 7;                                                    \
        _Pragma("unroll")                                                      \
        for (int sp = 0; sp < 4; sp++) {                                       \
            int chunk_ = 4 * sp + bgrp;                                        \
            uint32_t t0_, t1_, t2_, t3_;                                       \
            ldsm_x4(t0_, t1_, t2_, t3_, rb_ + ((chunk_ ^ r7_) << 4));          \
            dst[2 * sp][0] = t0_; dst[2 * sp][1] = t1_;                        \
            dst[2 * sp + 1][0] = t2_; dst[2 * sp + 1][1] = t3_;                \
        }                                                                      \
    } while (0)

// ---------------- pass 1: CTA per (b, k) within k-chunk [kbase, kbase+256) ----------------
__global__ __launch_bounds__(256, 2) void pass1(int kbase) {
    extern __shared__ unsigned char sm[];
    int tid = threadIdx.x, wid = tid >> 5, lane = tid & 31;
    int b = blockIdx.x >> 8, kidx = kbase + (blockIdx.x & 255);
    int akidx = (b << 9) + kidx;
    uint32_t smb = smem_u32(sm);

    {
        const uint4* gak = (const uint4*)(g_ak + (size_t)akidx * 32768);
        const uint4* gq0 = (const uint4*)(g_qh + (size_t)(b * 4 + 0) * 32768);
        const uint4* gq1 = (const uint4*)(g_qh + (size_t)(b * 4 + 1) * 32768);
        for (int i = tid; i < 2048; i += 256) {
            cp16(smb + A_OFF + i * 16, gak + i);
            cp16(smb + X0_OFF + i * 16, gq0 + i);
        }
        CP_COMMIT();
        for (int i = tid; i < 2048; i += 256) cp16(smb + X1_OFF + i * 16, gq1 + i);
        CP_COMMIT();
    }
    CP_WAIT(1);
    __syncthreads();

    // A fragments: warp wid owns u-rows [wid*16, +16), K=128 (8 k-steps)
    int u0 = wid * 16;
    uint32_t ahi[8][4];
    {
        int row = u0 + (lane & 7) + ((lane >> 3) & 1) * 8;
        int cpar = (lane >> 4) & 1;
        int r7 = lane & 7;
        uint32_t rbh = smb + A_OFF + row * 256;
#pragma unroll
        for (int s = 0; s < 8; s++) {
            int chunk = 2 * s + cpar;
            ldsm_x4(ahi[s][0], ahi[s][1], ahi[s][2], ahi[s][3], rbh + ((chunk ^ r7) << 4));
        }
    }
    __syncthreads();   // A region now free for y staging

    int r4 = lane >> 2, c4 = lane & 3;
    float mA = -1e30f, TA = 0.0f, mB = -1e30f, TB = 0.0f;
    uint4* dst = (uint4*)(g_xe + ((size_t)(b * KK + kidx) * TT) * QQ);

    for (int qt = 0; qt < 4; qt++) {
        int buf = qt & 1;
        uint32_t xb = smb + (buf ? X1_OFF : X0_OFF);
        // pipelined MMA + exp epilogue + inline flush to A region
        {
            int brow7 = lane & 7;
            int bgrp = lane >> 3;         // 0..3
            int uA = u0 + r4, uB = u0 + 8 + r4;
            unsigned char* yrA = sm + A_OFF + uA * 256;
            unsigned char* yrB = sm + A_OFF + uB * 256;
            int rotA = uA * 16, rotB = uB * 16;
            uint32_t bf0[8][2], bf1[8][2];
            LOAD_BF(bf0, 0);
#pragma unroll
            for (int nt = 0; nt < 16; nt++) {
                uint32_t (*cur)[2] = (nt & 1) ? bf1 : bf0;
                uint32_t (*nxt)[2] = (nt & 1) ? bf0 : bf1;
                float d0 = 0, d1 = 0, d2 = 0, d3 = 0;
#pragma unroll
                for (int s = 0; s < 8; s++)
                    mma16816(d0, d1, d2, d3, ahi[s][0], ahi[s][1], ahi[s][2], ahi[s][3],
                             cur[s][0], cur[s][1]);
                if (nt < 15) LOAD_BF(nxt, nt + 1);
                float y0 = d0 * __expf(d0), y1 = d1 * __expf(d1);
                float y2 = d2 * __expf(d2), y3 = d3 * __expf(d3);
                mA = fmaxf(mA, fmaxf(d0, d1));
                mB = fmaxf(mB, fmaxf(d2, d3));
                TA += fabsf(y0) + fabsf(y1);
                TB += fabsf(y2) + fabsf(y3);
                __half2 p0 = __floats2half2_rn(y0, y1);
                __half2 p1 = __floats2half2_rn(y2, y3);
                int qb = nt * 16 + 4 * c4;           // byte within 256B row
                *(uint32_t*)(yrA + ((qb + rotA) & 255)) = *(uint32_t*)&p0;
                *(uint32_t*)(yrB + ((qb + rotB) & 255)) = *(uint32_t*)&p1;
            }
        }
        __syncthreads();   // MMA done reading X(buf), y staged

        // prefetch qt+2 into the just-consumed buffer
        if (qt < 2) {
            const uint4* gqn = (const uint4*)(g_qh + (size_t)(b * 4 + qt + 2) * 32768);
            uint32_t xd = smb + (buf ? X1_OFF : X0_OFF);
            for (int i = tid; i < 2048; i += 256) cp16(xd + i * 16, gqn + i);
            CP_COMMIT();
        }
        // copy y staging -> g_xe (streaming stores)
        for (int idx = tid; idx < 2048; idx += 256) {
            int uu = idx >> 4, c = idx & 15;
            uint4 v = *(const uint4*)(sm + A_OFF + uu * 256 + ((c * 16 + uu * 16) & 255));
            __stcs(&dst[uu * 64 + qt * 16 + c], v);
        }
        if (qt < 3) {
            if (qt == 2) { CP_WAIT(0); } else { CP_WAIT(1); }
            __syncthreads();
        }
    }

    // reduce stats over the 4 lanes of each quad
    mA = fmaxf(mA, __shfl_xor_sync(0xFFFFFFFFu, mA, 1));
    mA = fmaxf(mA, __shfl_xor_sync(0xFFFFFFFFu, mA, 2));
    TA += __shfl_xor_sync(0xFFFFFFFFu, TA, 1);
    TA += __shfl_xor_sync(0xFFFFFFFFu, TA, 2);
    mB = fmaxf(mB, __shfl_xor_sync(0xFFFFFFFFu, mB, 1));
    mB = fmaxf(mB, __shfl_xor_sync(0xFFFFFFFFu, mB, 2));
    TB += __shfl_xor_sync(0xFFFFFFFFu, TB, 1);
    TB += __shfl_xor_sync(0xFFFFFFFFu, TB, 2);

    float* smm = (float*)(sm + STAT_OFF);
    float* smt = smm + 128;
    if (c4 == 0) {
        smm[u0 + r4] = mA;      smt[u0 + r4] = TA;
        smm[u0 + 8 + r4] = mB;  smt[u0 + 8 + r4] = TB;
    }
    __syncthreads();

    if (tid < 128) {
        float m = smm[tid], T = smt[tid];
        float vu = g_v[((size_t)b * KK + kidx) * TT + tid];
        g_w[((size_t)b * KK + kidx) * TT + tid] = vu / (T + __expf(m));
    }
}

// ---------------- pass 2: partial out over k-chunk of 32; kc in [kcbase, kcbase+8) ----------------
// grid: (64, BB*8), block 128 -> 8192 threads per (b,kc) slice
__global__ __launch_bounds__(128) void pass2(int kcbase) {
    __shared__ float ws[32 * 2];                 // w[k][u_local] for this CTA
    int bykc = blockIdx.y;                       // b*8 + kcl
    int b = bykc >> 3, kc = kcbase + (bykc & 7);
    int s = blockIdx.x * 128 + threadIdx.x;      // 8192 per slice
    int qg = s & 63, u = s >> 6;                 // u in [0,128)
    int ubase = (blockIdx.x * 128) >> 6;         // 2 u values per CTA
    if (threadIdx.x < 64) {
        int kk = threadIdx.x >> 1, ul = threadIdx.x & 1;
        ws[kk * 2 + ul] = g_w[((size_t)b * KK + kc * 32 + kk) * TT + ubase + ul];
    }
    __syncthreads();
    int ul = u - ubase;
    const uint4* src = (const uint4*)(g_xe + ((size_t)(b * KK + kc * 32) * TT + u) * QQ) + qg;
    const size_t kstride = (size_t)TT * QQ / 8;  // uint4 step per k
    float acc[8];
#pragma unroll
    for (int j = 0; j < 8; j++) acc[j] = 0.0f;
#pragma unroll 8
    for (int k = 0; k < 32; k++) {
        uint4 yv = __ldcs(&src[(size_t)k * kstride]);
        float wv = ws[k * 2 + ul];
        float2 f0 = __half22float2(*(__half2*)&yv.x);
        float2 f1 = __half22float2(*(__half2*)&yv.y);
        float2 f2 = __half22float2(*(__half2*)&yv.z);
        float2 f3 = __half22float2(*(__half2*)&yv.w);
        acc[0] = fmaf(wv, f0.x, acc[0]); acc[1] = fmaf(wv, f0.y, acc[1]);
        acc[2] = fmaf(wv, f1.x, acc[2]); acc[3] = fmaf(wv, f1.y, acc[3]);
        acc[4] = fmaf(wv, f2.x, acc[4]); acc[5] = fmaf(wv, f2.y, acc[5]);
        acc[6] = fmaf(wv, f3.x, acc[6]); acc[7] = fmaf(wv, f3.y, acc[7]);
    }
    float* dstp = g_accr + (size_t)kc * BB * QQ * TT;
    int q0 = qg * 8;
#pragma unroll
    for (int j = 0; j < 8; j++)
        dstp[((size_t)b * QQ + q0 + j) * TT + u] = acc[j];
}

// ---------------- launch ----------------
extern "C" void kernel_launch(void* const* d_in, const int* in_sizes, int n_in,
                              void* d_out, int out_size) {
    const float* q_in = (const float*)d_in[0];
    const float* k_in = (const float*)d_in[1];
    const float* v_in = (const float*)d_in[2];
    const float* Wk   = (const float*)d_in[3];
    const float* Wq   = (const float*)d_in[4];
    const float* Wv   = (const float*)d_in[5];
    const float* Wl   = (const float*)d_in[6];
    const float* Wo   = (const float*)d_in[7];
    float* out = (float*)d_out;

    const int SMEM_G = (128 * 132 + 32 * 132) * 4;   // 84480
    cudaFuncSetAttribute(gemm_out, cudaFuncAttributeMaxDynamicSharedMemorySize, SMEM_GO);
    cudaFuncSetAttribute(proj3,    cudaFuncAttributeMaxDynamicSharedMemorySize, SMEM_G);
    cudaFuncSetAttribute(pass1,    cudaFuncAttributeMaxDynamicSharedMemorySize, P1_SMEM);

    cudaStream_t s1;
    cudaStreamCreateWithFlags(&s1, cudaStreamNonBlocking);
    cudaEvent_t eA, eB, eJ;
    cudaEventCreateWithFlags(&eA, cudaEventDisableTiming);
    cudaEventCreateWithFlags(&eB, cudaEventDisableTiming);
    cudaEventCreateWithFlags(&eJ, cudaEventDisableTiming);

    proj3<<<dim3(32, 3), 256, SMEM_G>>>(q_in, Wq, k_in, Wk, v_in, Wv);
    prep_images<<<BB * KK + 8, 256>>>(Wl);

    pass1<<<BB * 256, 256, P1_SMEM>>>(0);       // k-half A: k in [0,256)
    cudaEventRecord(eA, 0);
    pass1<<<BB * 256, 256, P1_SMEM>>>(256);     // k-half B: k in [256,512)
    cudaEventRecord(eB, 0);

    cudaStreamWaitEvent(s1, eA, 0);
    pass2<<<dim3(64, BB * 8), 128, 0, s1>>>(0);  // kc 0..7 (k < 256), overlaps pass1 half B
    cudaStreamWaitEvent(s1, eB, 0);
    pass2<<<dim3(64, BB * 8), 128, 0, s1>>>(8);  // kc 8..15
    cudaEventRecord(eJ, s1);
    cudaStreamWaitEvent(0, eJ, 0);

    gemm_out<<<64, 256, SMEM_GO>>>(Wo, out);

    cudaEventDestroy(eA);
    cudaEventDestroy(eB);
    cudaEventDestroy(eJ);
    cudaStreamDestroy(s1);
}

// round 15
// speedup vs baseline: 1.0625x; 1.0625x over previous
#include <cuda_runtime.h>
#include <cuda_fp16.h>
#include <cstdint>

#define BB 2
#define KK 512
#define QQ 512
#define TT 128
#define NREP 16

// ---------------- device scratch ----------------
__device__ float g_k[BB * KK * TT];
__device__ float g_q[BB * QQ * TT];
__device__ float g_v[BB * KK * TT];
__device__ float g_w[BB * KK * TT];                  // per (b,k,u) scale v_u/(T+e^m)
__device__ float g_accr[NREP * BB * QQ * TT];        // k-split partial sums
__device__ __half g_xe[(size_t)BB * KK * TT * QQ];   // 128MB unscaled y = x*e^x
__device__ unsigned char g_ak[(size_t)BB * KK * 32768];  // 32MB swizzled fp16 Wl*k images
__device__ unsigned char g_qh[BB * 4 * 32768];           // 256KB swizzled fp16 q tiles

// ---------------- helpers ----------------
__device__ __forceinline__ uint32_t smem_u32(const void* p) {
    uint32_t a;
    asm("{ .reg .u64 t; cvta.to.shared.u64 t, %1; cvt.u32.u64 %0, t; }" : "=r"(a) : "l"(p));
    return a;
}
__device__ __forceinline__ void ldsm_x4(uint32_t& r0, uint32_t& r1, uint32_t& r2, uint32_t& r3,
                                        uint32_t addr) {
    asm volatile("ldmatrix.sync.aligned.m8n8.x4.shared.b16 {%0,%1,%2,%3}, [%4];"
                 : "=r"(r0), "=r"(r1), "=r"(r2), "=r"(r3) : "r"(addr));
}
__device__ __forceinline__ void mma16816(float& d0, float& d1, float& d2, float& d3,
                                         uint32_t a0, uint32_t a1, uint32_t a2, uint32_t a3,
                                         uint32_t b0, uint32_t b1) {
    asm volatile("mma.sync.aligned.m16n8k16.row.col.f32.f16.f16.f32 "
                 "{%0,%1,%2,%3}, {%4,%5,%6,%7}, {%8,%9}, {%0,%1,%2,%3};"
                 : "+f"(d0), "+f"(d1), "+f"(d2), "+f"(d3)
                 : "r"(a0), "r"(a1), "r"(a2), "r"(a3), "r"(b0), "r"(b1));
}
__device__ __forceinline__ void cp16(uint32_t smem, const void* g) {
    asm volatile("cp.async.cg.shared.global [%0], [%1], 16;" :: "r"(smem), "l"(g));
}
#define CP_COMMIT() asm volatile("cp.async.commit_group;" ::: "memory")
#define CP_WAIT(N)  asm volatile("cp.async.wait_group %0;" :: "n"(N) : "memory")

// smem byte layout for pass1 (total 66560 -> 3 CTAs/SM)
#define A_OFF    0          // 32KB: A_k image; reused as y staging after frag load
#define X_OFF    32768      // 32KB X buffer (single)
#define STAT_OFF 65536      // m[128], T[128] = 1KB
#define P1_SMEM  66560

// ---------------- prep: build swizzled fp16 images ----------------
__global__ __launch_bounds__(256) void prep_images(const float* __restrict__ Wl) {
    int blk = blockIdx.x;
    int tid = threadIdx.x;
    int r = tid >> 1, h = tid & 1;
    int r7 = r & 7;
    if (blk < BB * KK) {
        int b = blk >> 9, k = blk & 511;
        const float4* wrow = (const float4*)(Wl + (size_t)r * TT + h * 64);
        const float4* krow = (const float4*)(g_k + ((size_t)b * KK + k) * TT + h * 64);
        unsigned char* arow = g_ak + (size_t)blk * 32768 + r * 256;
#pragma unroll
        for (int c8 = 0; c8 < 8; c8++) {
            float4 qa = wrow[c8 * 2], qb = wrow[c8 * 2 + 1];
            float4 ka = krow[c8 * 2], kb = krow[c8 * 2 + 1];
            __half2 h0 = __floats2half2_rn(qa.x * ka.x, qa.y * ka.y);
            __half2 h1 = __floats2half2_rn(qa.z * ka.z, qa.w * ka.w);
            __half2 h2 = __floats2half2_rn(qb.x * kb.x, qb.y * kb.y);
            __half2 h3 = __floats2half2_rn(qb.z * kb.z, qb.w * kb.w);
            int chunk = h * 8 + c8;
            uint4 pk;
            pk.x = *(uint32_t*)&h0; pk.y = *(uint32_t*)&h1;
            pk.z = *(uint32_t*)&h2; pk.w = *(uint32_t*)&h3;
            *(uint4*)(arow + ((chunk ^ r7) << 4)) = pk;
        }
    } else {
        int i = blk - BB * KK;            // 0..7: b = i>>2, qt = i&3
        int b = i >> 2, qt = i & 3;
        const float4* qrow = (const float4*)(g_q + ((size_t)b * QQ + qt * 128 + r) * TT + h * 64);
        unsigned char* xrow = g_qh + (size_t)i * 32768 + r * 256;
#pragma unroll
        for (int c8 = 0; c8 < 8; c8++) {
            float4 qa = qrow[c8 * 2], qb = qrow[c8 * 2 + 1];
            __half2 h0 = __floats2half2_rn(qa.x, qa.y);
            __half2 h1 = __floats2half2_rn(qa.z, qa.w);
            __half2 h2 = __floats2half2_rn(qb.x, qb.y);
            __half2 h3 = __floats2half2_rn(qb.z, qb.w);
            int chunk = h * 8 + c8;
            uint4 pk;
            pk.x = *(uint32_t*)&h0; pk.y = *(uint32_t*)&h1;
            pk.z = *(uint32_t*)&h2; pk.w = *(uint32_t*)&h3;
            *(uint4*)(xrow + ((chunk ^ r7) << 4)) = pk;
        }
    }
}

// ---------------- fp32 GEMM 32-row tiles: out[r,u] = sum_t in[r,t]*W[u,t] ----------------
__device__ __forceinline__ void gemm32_body(const float* __restrict__ in,
                                            const float* __restrict__ W,
                                            float* __restrict__ out, int r0) {
    extern __shared__ float smf[];
    float* sW = smf;                 // [128][132]
    float* sI = smf + 128 * 132;     // [32][132]
    int tid = threadIdx.x;
    for (int i = tid; i < 128 * 128; i += 256) { int u = i >> 7, t = i & 127; sW[u * 132 + t] = W[i]; }
    for (int i = tid; i < 32 * 128;  i += 256) {
        int r = i >> 7, t = i & 127;
        sI[r * 132 + t] = in[(size_t)r0 * 128 + i];
    }
    __syncthreads();
    int tx = tid & 15, ty = tid >> 4;
    float acc[2][8];
#pragma unroll
    for (int i = 0; i < 2; i++)
#pragma unroll
        for (int j = 0; j < 8; j++) acc[i][j] = 0.0f;
    for (int t = 0; t < 128; t += 4) {
        float4 a0 = *(const float4*)&sI[(ty * 2 + 0) * 132 + t];
        float4 a1 = *(const float4*)&sI[(ty * 2 + 1) * 132 + t];
#pragma unroll
        for (int j = 0; j < 8; j++) {
            float4 bv = *(const float4*)&sW[(tx + 16 * j) * 132 + t];
            acc[0][j] = fmaf(a0.x, bv.x, acc[0][j]); acc[0][j] = fmaf(a0.y, bv.y, acc[0][j]);
            acc[0][j] = fmaf(a0.z, bv.z, acc[0][j]); acc[0][j] = fmaf(a0.w, bv.w, acc[0][j]);
            acc[1][j] = fmaf(a1.x, bv.x, acc[1][j]); acc[1][j] = fmaf(a1.y, bv.y, acc[1][j]);
            acc[1][j] = fmaf(a1.z, bv.z, acc[1][j]); acc[1][j] = fmaf(a1.w, bv.w, acc[1][j]);
        }
    }
#pragma unroll
    for (int i = 0; i < 2; i++)
#pragma unroll
        for (int j = 0; j < 8; j++)
            out[(size_t)(r0 + ty * 2 + i) * 128 + tx + 16 * j] = acc[i][j];
}

// ---------------- gemm_out: 16-row tiles, folds NREP replica sum ----------------
#define SMEM_GO ((128 * 132 + 16 * 132) * 4)
__global__ __launch_bounds__(256) void gemm_out(const float* __restrict__ W,
                                                float* __restrict__ out) {
    extern __shared__ float smf[];
    float* sW = smf;                 // [128][132]
    float* sI = smf + 128 * 132;     // [16][132]
    int tid = threadIdx.x;
    int r0 = blockIdx.x * 16;
    for (int i = tid; i < 128 * 128; i += 256) { int u = i >> 7, t = i & 127; sW[u * 132 + t] = W[i]; }
    for (int i = tid; i < 16 * 128; i += 256) {
        int r = i >> 7, t = i & 127;
        const size_t off = (size_t)r0 * 128 + i;
        const size_t st = (size_t)BB * QQ * TT;
        float v = 0.0f;
#pragma unroll
        for (int rr = 0; rr < NREP; rr++) v += g_accr[off + (size_t)rr * st];
        sI[r * 132 + t] = v;
    }
    __syncthreads();
    int tx = tid & 15, ty = tid >> 4;   // r = r0+ty, u = tx + 16*j
    float acc[8];
#pragma unroll
    for (int j = 0; j < 8; j++) acc[j] = 0.0f;
    for (int t = 0; t < 128; t += 4) {
        float4 a0 = *(const float4*)&sI[ty * 132 + t];
#pragma unroll
        for (int j = 0; j < 8; j++) {
            float4 bv = *(const float4*)&sW[(tx + 16 * j) * 132 + t];
            acc[j] = fmaf(a0.x, bv.x, acc[j]); acc[j] = fmaf(a0.y, bv.y, acc[j]);
            acc[j] = fmaf(a0.z, bv.z, acc[j]); acc[j] = fmaf(a0.w, bv.w, acc[j]);
        }
    }
#pragma unroll
    for (int j = 0; j < 8; j++)
        out[(size_t)(r0 + ty) * 128 + tx + 16 * j] = acc[j];
}

__global__ __launch_bounds__(256) void proj3(const float* __restrict__ qi, const float* __restrict__ Wq,
                                             const float* __restrict__ ki, const float* __restrict__ Wk,
                                             const float* __restrict__ vi, const float* __restrict__ Wv) {
    int r0 = blockIdx.x * 32;
    if (blockIdx.y == 0)      gemm32_body(qi, Wq, g_q, r0);
    else if (blockIdx.y == 1) gemm32_body(ki, Wk, g_k, r0);
    else                      gemm32_body(vi, Wv, g_v, r0);
}

// load B-fragments for one nt row-block
#define LOAD_BF(dst, ntv)                                                      \
    do {                                                                       \
        int row_ = (ntv) * 8 + brow7;                                          \
        uint32_t rb_ = xb + row_ * 256;                                        \
        int r7_ = row_ & 7;                                                    \
        _Pragma("unroll")                                                      \
        for (int sp = 0; sp < 4; sp++) {                                       \
            int chunk_ = 4 * sp + bgrp;                                        \
            uint32_t t0_, t1_, t2_, t3_;                                       \
            ldsm_x4(t0_, t1_, t2_, t3_, rb_ + ((chunk_ ^ r7_) << 4));          \
            dst[2 * sp][0] = t0_; dst[2 * sp][1] = t1_;                        \
            dst[2 * sp + 1][0] = t2_; dst[2 * sp + 1][1] = t3_;                \
        }                                                                      \
    } while (0)

// ---------------- pass 1: CTA per (b,k); 3 CTAs/SM ----------------
__global__ __launch_bounds__(256, 3) void pass1() {
    extern __shared__ unsigned char sm[];
    int tid = threadIdx.x, wid = tid >> 5, lane = tid & 31;
    int b = blockIdx.x >> 9, kidx = blockIdx.x & 511;
    uint32_t smb = smem_u32(sm);

    {
        const uint4* gak = (const uint4*)(g_ak + (size_t)blockIdx.x * 32768);
        const uint4* gq0 = (const uint4*)(g_qh + (size_t)(b * 4 + 0) * 32768);
        for (int i = tid; i < 2048; i += 256) {
            cp16(smb + A_OFF + i * 16, gak + i);
            cp16(smb + X_OFF + i * 16, gq0 + i);
        }
        CP_COMMIT();
    }
    CP_WAIT(0);
    __syncthreads();

    // A fragments: warp wid owns u-rows [wid*16, +16), K=128 (8 k-steps)
    int u0 = wid * 16;
    uint32_t ahi[8][4];
    {
        int row = u0 + (lane & 7) + ((lane >> 3) & 1) * 8;
        int cpar = (lane >> 4) & 1;
        int r7 = lane & 7;
        uint32_t rbh = smb + A_OFF + row * 256;
#pragma unroll
        for (int s = 0; s < 8; s++) {
            int chunk = 2 * s + cpar;
            ldsm_x4(ahi[s][0], ahi[s][1], ahi[s][2], ahi[s][3], rbh + ((chunk ^ r7) << 4));
        }
    }
    __syncthreads();   // A region now free for y staging

    int r4 = lane >> 2, c4 = lane & 3;
    float mA = -1e30f, TA = 0.0f, mB = -1e30f, TB = 0.0f;
    uint4* dst = (uint4*)(g_xe + ((size_t)(b * KK + kidx) * TT) * QQ);
    uint32_t xb = smb + X_OFF;

    for (int qt = 0; qt < 4; qt++) {
        // MMA + exp epilogue + inline flush to A region (bf loaded inline per nt)
        {
            int brow7 = lane & 7;
            int bgrp = lane >> 3;         // 0..3
            int uA = u0 + r4, uB = u0 + 8 + r4;
            unsigned char* yrA = sm + A_OFF + uA * 256;
            unsigned char* yrB = sm + A_OFF + uB * 256;
            int rotA = uA * 16, rotB = uB * 16;
#pragma unroll
            for (int nt = 0; nt < 16; nt++) {
                uint32_t bf[8][2];
                LOAD_BF(bf, nt);
                float d0 = 0, d1 = 0, d2 = 0, d3 = 0;
#pragma unroll
                for (int s = 0; s < 8; s++)
                    mma16816(d0, d1, d2, d3, ahi[s][0], ahi[s][1], ahi[s][2], ahi[s][3],
                             bf[s][0], bf[s][1]);
                float y0 = d0 * __expf(d0), y1 = d1 * __expf(d1);
                float y2 = d2 * __expf(d2), y3 = d3 * __expf(d3);
                mA = fmaxf(mA, fmaxf(d0, d1));
                mB = fmaxf(mB, fmaxf(d2, d3));
                TA += fabsf(y0) + fabsf(y1);
                TB += fabsf(y2) + fabsf(y3);
                __half2 p0 = __floats2half2_rn(y0, y1);
                __half2 p1 = __floats2half2_rn(y2, y3);
                int qb = nt * 16 + 4 * c4;           // byte within 256B row
                *(uint32_t*)(yrA + ((qb + rotA) & 255)) = *(uint32_t*)&p0;
                *(uint32_t*)(yrB + ((qb + rotB) & 255)) = *(uint32_t*)&p1;
            }
        }
        __syncthreads();   // MMA done reading X, y staged

        // refill X with qt+1 (overlaps copy-out below)
        if (qt < 3) {
            const uint4* gqn = (const uint4*)(g_qh + (size_t)(b * 4 + qt + 1) * 32768);
            for (int i = tid; i < 2048; i += 256) cp16(smb + X_OFF + i * 16, gqn + i);
            CP_COMMIT();
        }
        // copy y staging -> g_xe (streaming stores)
        for (int idx = tid; idx < 2048; idx += 256) {
            int uu = idx >> 4, c = idx & 15;
            uint4 v = *(const uint4*)(sm + A_OFF + uu * 256 + ((c * 16 + uu * 16) & 255));
            __stcs(&dst[uu * 64 + qt * 16 + c], v);
        }
        if (qt < 3) CP_WAIT(0);
        __syncthreads();
    }

    // reduce stats over the 4 lanes of each quad
    mA = fmaxf(mA, __shfl_xor_sync(0xFFFFFFFFu, mA, 1));
    mA = fmaxf(mA, __shfl_xor_sync(0xFFFFFFFFu, mA, 2));
    TA += __shfl_xor_sync(0xFFFFFFFFu, TA, 1);
    TA += __shfl_xor_sync(0xFFFFFFFFu, TA, 2);
    mB = fmaxf(mB, __shfl_xor_sync(0xFFFFFFFFu, mB, 1));
    mB = fmaxf(mB, __shfl_xor_sync(0xFFFFFFFFu, mB, 2));
    TB += __shfl_xor_sync(0xFFFFFFFFu, TB, 1);
    TB += __shfl_xor_sync(0xFFFFFFFFu, TB, 2);

    float* smm = (float*)(sm + STAT_OFF);
    float* smt = smm + 128;
    if (c4 == 0) {
        smm[u0 + r4] = mA;      smt[u0 + r4] = TA;
        smm[u0 + 8 + r4] = mB;  smt[u0 + 8 + r4] = TB;
    }
    __syncthreads();

    if (tid < 128) {
        float m = smm[tid], T = smt[tid];
        float vu = g_v[((size_t)b * KK + kidx) * TT + tid];
        g_w[((size_t)b * KK + kidx) * TT + tid] = vu / (T + __expf(m));
    }
}

// ---------------- pass 2: partial out over k-chunk of 32; 16 replicas ----------------
// grid: (64, BB*NREP), block 128 -> 8192 threads per (b,kc) slice
__global__ __launch_bounds__(128) void pass2() {
    __shared__ float ws[32 * 2];                 // w[k][u_local] for this CTA
    int bykc = blockIdx.y;                       // b*16 + kc
    int b = bykc >> 4, kc = bykc & 15;
    int s = blockIdx.x * 128 + threadIdx.x;      // 8192 per slice
    int qg = s & 63, u = s >> 6;                 // u in [0,128)
    int ubase = (blockIdx.x * 128) >> 6;         // 2 u values per CTA
    if (threadIdx.x < 64) {
        int kk = threadIdx.x >> 1, ul = threadIdx.x & 1;
        ws[kk * 2 + ul] = g_w[((size_t)b * KK + kc * 32 + kk) * TT + ubase + ul];
    }
    __syncthreads();
    int ul = u - ubase;
    const uint4* src = (const uint4*)(g_xe + ((size_t)(b * KK + kc * 32) * TT + u) * QQ) + qg;
    const size_t kstride = (size_t)TT * QQ / 8;  // uint4 step per k
    float acc[8];
#pragma unroll
    for (int j = 0; j < 8; j++) acc[j] = 0.0f;
#pragma unroll 8
    for (int k = 0; k < 32; k++) {
        uint4 yv = __ldcs(&src[(size_t)k * kstride]);
        float wv = ws[k * 2 + ul];
        float2 f0 = __half22float2(*(__half2*)&yv.x);
        float2 f1 = __half22float2(*(__half2*)&yv.y);
        float2 f2 = __half22float2(*(__half2*)&yv.z);
        float2 f3 = __half22float2(*(__half2*)&yv.w);
        acc[0] = fmaf(wv, f0.x, acc[0]); acc[1] = fmaf(wv, f0.y, acc[1]);
        acc[2] = fmaf(wv, f1.x, acc[2]); acc[3] = fmaf(wv, f1.y, acc[3]);
        acc[4] = fmaf(wv, f2.x, acc[4]); acc[5] = fmaf(wv, f2.y, acc[5]);
        acc[6] = fmaf(wv, f3.x, acc[6]); acc[7] = fmaf(wv, f3.y, acc[7]);
    }
    float* dstp = g_accr + (size_t)kc * BB * QQ * TT;
    int q0 = qg * 8;
#pragma unroll
    for (int j = 0; j < 8; j++)
        dstp[((size_t)b * QQ + q0 + j) * TT + u] = acc[j];
}

// ---------------- launch ----------------
extern "C" void kernel_launch(void* const* d_in, const int* in_sizes, int n_in,
                              void* d_out, int out_size) {
    const float* q_in = (const float*)d_in[0];
    const float* k_in = (const float*)d_in[1];
    const float* v_in = (const float*)d_in[2];
    const float* Wk   = (const float*)d_in[3];
    const float* Wq   = (const float*)d_in[4];
    const float* Wv   = (const float*)d_in[5];
    const float* Wl   = (const float*)d_in[6];
    const float* Wo   = (const float*)d_in[7];
    float* out = (float*)d_out;

    const int SMEM_G = (128 * 132 + 32 * 132) * 4;   // 84480
    cudaFuncSetAttribute(gemm_out, cudaFuncAttributeMaxDynamicSharedMemorySize, SMEM_GO);
    cudaFuncSetAttribute(proj3,    cudaFuncAttributeMaxDynamicSharedMemorySize, SMEM_G);
    cudaFuncSetAttribute(pass1,    cudaFuncAttributeMaxDynamicSharedMemorySize, P1_SMEM);

    proj3<<<dim3(32, 3), 256, SMEM_G>>>(q_in, Wq, k_in, Wk, v_in, Wv);
    prep_images<<<BB * KK + 8, 256>>>(Wl);
    pass1<<<BB * KK, 256, P1_SMEM>>>();
    pass2<<<dim3(64, BB * NREP), 128>>>();
    gemm_out<<<64, 256, SMEM_GO>>>(Wo, out);
}

// round 16
// speedup vs baseline: 1.0651x; 1.0025x over previous
#include <cuda_runtime.h>
#include <cuda_fp16.h>
#include <cstdint>

#define BB 2
#define KK 512
#define QQ 512
#define TT 128
#define NREP 16

// ---------------- device scratch ----------------
__device__ float g_k[BB * KK * TT];
__device__ float g_q[BB * QQ * TT];
__device__ float g_v[BB * KK * TT];
__device__ float g_w[BB * KK * TT];                  // per (b,k,u) scale v_u/(T+e^m)
__device__ float g_accr[NREP * BB * QQ * TT];        // k-split partial sums
__device__ __half g_xe[(size_t)BB * KK * TT * QQ];   // 128MB unscaled y = x*e^x
__device__ unsigned char g_ak[(size_t)BB * KK * 32768];  // 32MB swizzled fp16 Wl*k images
__device__ unsigned char g_qh[BB * 4 * 32768];           // 256KB swizzled fp16 q tiles

// ---------------- helpers ----------------
__device__ __forceinline__ uint32_t smem_u32(const void* p) {
    uint32_t a;
    asm("{ .reg .u64 t; cvta.to.shared.u64 t, %1; cvt.u32.u64 %0, t; }" : "=r"(a) : "l"(p));
    return a;
}
__device__ __forceinline__ void ldsm_x4(uint32_t& r0, uint32_t& r1, uint32_t& r2, uint32_t& r3,
                                        uint32_t addr) {
    asm volatile("ldmatrix.sync.aligned.m8n8.x4.shared.b16 {%0,%1,%2,%3}, [%4];"
                 : "=r"(r0), "=r"(r1), "=r"(r2), "=r"(r3) : "r"(addr));
}
__device__ __forceinline__ void mma16816(float& d0, float& d1, float& d2, float& d3,
                                         uint32_t a0, uint32_t a1, uint32_t a2, uint32_t a3,
                                         uint32_t b0, uint32_t b1) {
    asm volatile("mma.sync.aligned.m16n8k16.row.col.f32.f16.f16.f32 "
                 "{%0,%1,%2,%3}, {%4,%5,%6,%7}, {%8,%9}, {%0,%1,%2,%3};"
                 : "+f"(d0), "+f"(d1), "+f"(d2), "+f"(d3)
                 : "r"(a0), "r"(a1), "r"(a2), "r"(a3), "r"(b0), "r"(b1));
}
__device__ __forceinline__ void cp16(uint32_t smem, const void* g) {
    asm volatile("cp.async.cg.shared.global [%0], [%1], 16;" :: "r"(smem), "l"(g));
}
#define CP_COMMIT() asm volatile("cp.async.commit_group;" ::: "memory")
#define CP_WAIT(N)  asm volatile("cp.async.wait_group %0;" :: "n"(N) : "memory")

// smem byte layout for pass1 (total 66560 -> 3 CTAs/SM)
#define A_OFF    0          // 32KB: A_k image; reused as y staging after frag load
#define X_OFF    32768      // 32KB X buffer (single)
#define STAT_OFF 65536      // m[128], T[128] = 1KB
#define P1_SMEM  66560

// ---------------- prep: build swizzled fp16 images ----------------
__global__ __launch_bounds__(256) void prep_images(const float* __restrict__ Wl) {
    int blk = blockIdx.x;
    int tid = threadIdx.x;
    int r = tid >> 1, h = tid & 1;
    int r7 = r & 7;
    if (blk < BB * KK) {
        int b = blk >> 9, k = blk & 511;
        const float4* wrow = (const float4*)(Wl + (size_t)r * TT + h * 64);
        const float4* krow = (const float4*)(g_k + ((size_t)b * KK + k) * TT + h * 64);
        unsigned char* arow = g_ak + (size_t)blk * 32768 + r * 256;
#pragma unroll
        for (int c8 = 0; c8 < 8; c8++) {
            float4 qa = wrow[c8 * 2], qb = wrow[c8 * 2 + 1];
            float4 ka = krow[c8 * 2], kb = krow[c8 * 2 + 1];
            __half2 h0 = __floats2half2_rn(qa.x * ka.x, qa.y * ka.y);
            __half2 h1 = __floats2half2_rn(qa.z * ka.z, qa.w * ka.w);
            __half2 h2 = __floats2half2_rn(qb.x * kb.x, qb.y * kb.y);
            __half2 h3 = __floats2half2_rn(qb.z * kb.z, qb.w * kb.w);
            int chunk = h * 8 + c8;
            uint4 pk;
            pk.x = *(uint32_t*)&h0; pk.y = *(uint32_t*)&h1;
            pk.z = *(uint32_t*)&h2; pk.w = *(uint32_t*)&h3;
            *(uint4*)(arow + ((chunk ^ r7) << 4)) = pk;
        }
    } else {
        int i = blk - BB * KK;            // 0..7: b = i>>2, qt = i&3
        int b = i >> 2, qt = i & 3;
        const float4* qrow = (const float4*)(g_q + ((size_t)b * QQ + qt * 128 + r) * TT + h * 64);
        unsigned char* xrow = g_qh + (size_t)i * 32768 + r * 256;
#pragma unroll
        for (int c8 = 0; c8 < 8; c8++) {
            float4 qa = qrow[c8 * 2], qb = qrow[c8 * 2 + 1];
            __half2 h0 = __floats2half2_rn(qa.x, qa.y);
            __half2 h1 = __floats2half2_rn(qa.z, qa.w);
            __half2 h2 = __floats2half2_rn(qb.x, qb.y);
            __half2 h3 = __floats2half2_rn(qb.z, qb.w);
            int chunk = h * 8 + c8;
            uint4 pk;
            pk.x = *(uint32_t*)&h0; pk.y = *(uint32_t*)&h1;
            pk.z = *(uint32_t*)&h2; pk.w = *(uint32_t*)&h3;
            *(uint4*)(xrow + ((chunk ^ r7) << 4)) = pk;
        }
    }
}

// ---------------- fp32 GEMM 32-row tiles: out[r,u] = sum_t in[r,t]*W[u,t] ----------------
__device__ __forceinline__ void gemm32_body(const float* __restrict__ in,
                                            const float* __restrict__ W,
                                            float* __restrict__ out, int r0) {
    extern __shared__ float smf[];
    float* sW = smf;                 // [128][132]
    float* sI = smf + 128 * 132;     // [32][132]
    int tid = threadIdx.x;
    for (int i = tid; i < 128 * 128; i += 256) { int u = i >> 7, t = i & 127; sW[u * 132 + t] = W[i]; }
    for (int i = tid; i < 32 * 128;  i += 256) {
        int r = i >> 7, t = i & 127;
        sI[r * 132 + t] = in[(size_t)r0 * 128 + i];
    }
    __syncthreads();
    int tx = tid & 15, ty = tid >> 4;
    float acc[2][8];
#pragma unroll
    for (int i = 0; i < 2; i++)
#pragma unroll
        for (int j = 0; j < 8; j++) acc[i][j] = 0.0f;
    for (int t = 0; t < 128; t += 4) {
        float4 a0 = *(const float4*)&sI[(ty * 2 + 0) * 132 + t];
        float4 a1 = *(const float4*)&sI[(ty * 2 + 1) * 132 + t];
#pragma unroll
        for (int j = 0; j < 8; j++) {
            float4 bv = *(const float4*)&sW[(tx + 16 * j) * 132 + t];
            acc[0][j] = fmaf(a0.x, bv.x, acc[0][j]); acc[0][j] = fmaf(a0.y, bv.y, acc[0][j]);
            acc[0][j] = fmaf(a0.z, bv.z, acc[0][j]); acc[0][j] = fmaf(a0.w, bv.w, acc[0][j]);
            acc[1][j] = fmaf(a1.x, bv.x, acc[1][j]); acc[1][j] = fmaf(a1.y, bv.y, acc[1][j]);
            acc[1][j] = fmaf(a1.z, bv.z, acc[1][j]); acc[1][j] = fmaf(a1.w, bv.w, acc[1][j]);
        }
    }
#pragma unroll
    for (int i = 0; i < 2; i++)
#pragma unroll
        for (int j = 0; j < 8; j++)
            out[(size_t)(r0 + ty * 2 + i) * 128 + tx + 16 * j] = acc[i][j];
}

// ---------------- gemm_out: 16-row tiles, folds NREP replica sum ----------------
#define SMEM_GO ((128 * 132 + 16 * 132) * 4)
__global__ __launch_bounds__(256) void gemm_out(const float* __restrict__ W,
                                                float* __restrict__ out) {
    extern __shared__ float smf[];
    float* sW = smf;                 // [128][132]
    float* sI = smf + 128 * 132;     // [16][132]
    int tid = threadIdx.x;
    int r0 = blockIdx.x * 16;
    for (int i = tid; i < 128 * 128; i += 256) { int u = i >> 7, t = i & 127; sW[u * 132 + t] = W[i]; }
    for (int i = tid; i < 16 * 128; i += 256) {
        int r = i >> 7, t = i & 127;
        const size_t off = (size_t)r0 * 128 + i;
        const size_t st = (size_t)BB * QQ * TT;
        float v = 0.0f;
#pragma unroll
        for (int rr = 0; rr < NREP; rr++) v += g_accr[off + (size_t)rr * st];
        sI[r * 132 + t] = v;
    }
    __syncthreads();
    int tx = tid & 15, ty = tid >> 4;   // r = r0+ty, u = tx + 16*j
    float acc[8];
#pragma unroll
    for (int j = 0; j < 8; j++) acc[j] = 0.0f;
    for (int t = 0; t < 128; t += 4) {
        float4 a0 = *(const float4*)&sI[ty * 132 + t];
#pragma unroll
        for (int j = 0; j < 8; j++) {
            float4 bv = *(const float4*)&sW[(tx + 16 * j) * 132 + t];
            acc[j] = fmaf(a0.x, bv.x, acc[j]); acc[j] = fmaf(a0.y, bv.y, acc[j]);
            acc[j] = fmaf(a0.z, bv.z, acc[j]); acc[j] = fmaf(a0.w, bv.w, acc[j]);
        }
    }
#pragma unroll
    for (int j = 0; j < 8; j++)
        out[(size_t)(r0 + ty) * 128 + tx + 16 * j] = acc[j];
}

__global__ __launch_bounds__(256) void proj3(const float* __restrict__ qi, const float* __restrict__ Wq,
                                             const float* __restrict__ ki, const float* __restrict__ Wk,
                                             const float* __restrict__ vi, const float* __restrict__ Wv) {
    int r0 = blockIdx.x * 32;
    if (blockIdx.y == 0)      gemm32_body(qi, Wq, g_q, r0);
    else if (blockIdx.y == 1) gemm32_body(ki, Wk, g_k, r0);
    else                      gemm32_body(vi, Wv, g_v, r0);
}

// load B-fragments for one nt row-block
#define LOAD_BF(dst, ntv)                                                      \
    do {                                                                       \
        int row_ = (ntv) * 8 + brow7;                                          \
        uint32_t rb_ = xb + row_ * 256;                                        \
        int r7_ = row_ & 7;                                                    \
        _Pragma("unroll")                                                      \
        for (int sp = 0; sp < 4; sp++) {                                       \
            int chunk_ = 4 * sp + bgrp;                                        \
            uint32_t t0_, t1_, t2_, t3_;                                       \
            ldsm_x4(t0_, t1_, t2_, t3_, rb_ + ((chunk_ ^ r7_) << 4));          \
            dst[2 * sp][0] = t0_; dst[2 * sp][1] = t1_;                        \
            dst[2 * sp + 1][0] = t2_; dst[2 * sp + 1][1] = t3_;                \
        }                                                                      \
    } while (0)

// ---------------- pass 1: CTA per (b,k); 3 CTAs/SM; pipelined B fragments ----------------
__global__ __launch_bounds__(256, 3) void pass1() {
    extern __shared__ unsigned char sm[];
    int tid = threadIdx.x, wid = tid >> 5, lane = tid & 31;
    int b = blockIdx.x >> 9, kidx = blockIdx.x & 511;
    uint32_t smb = smem_u32(sm);

    {
        const uint4* gak = (const uint4*)(g_ak + (size_t)blockIdx.x * 32768);
        const uint4* gq0 = (const uint4*)(g_qh + (size_t)(b * 4 + 0) * 32768);
        for (int i = tid; i < 2048; i += 256) {
            cp16(smb + A_OFF + i * 16, gak + i);
            cp16(smb + X_OFF + i * 16, gq0 + i);
        }
        CP_COMMIT();
    }
    CP_WAIT(0);
    __syncthreads();

    // A fragments: warp wid owns u-rows [wid*16, +16), K=128 (8 k-steps)
    int u0 = wid * 16;
    uint32_t ahi[8][4];
    {
        int row = u0 + (lane & 7) + ((lane >> 3) & 1) * 8;
        int cpar = (lane >> 4) & 1;
        int r7 = lane & 7;
        uint32_t rbh = smb + A_OFF + row * 256;
#pragma unroll
        for (int s = 0; s < 8; s++) {
            int chunk = 2 * s + cpar;
            ldsm_x4(ahi[s][0], ahi[s][1], ahi[s][2], ahi[s][3], rbh + ((chunk ^ r7) << 4));
        }
    }
    __syncthreads();   // A region now free for y staging

    int r4 = lane >> 2, c4 = lane & 3;
    float mA = -1e30f, TA = 0.0f, mB = -1e30f, TB = 0.0f;
    uint4* dst = (uint4*)(g_xe + ((size_t)(b * KK + kidx) * TT) * QQ);
    uint32_t xb = smb + X_OFF;

    for (int qt = 0; qt < 4; qt++) {
        // pipelined MMA + exp epilogue + inline flush to A region
        {
            int brow7 = lane & 7;
            int bgrp = lane >> 3;         // 0..3
            int uA = u0 + r4, uB = u0 + 8 + r4;
            unsigned char* yrA = sm + A_OFF + uA * 256;
            unsigned char* yrB = sm + A_OFF + uB * 256;
            int rotA = uA * 16, rotB = uB * 16;
            uint32_t bf0[8][2], bf1[8][2];
            LOAD_BF(bf0, 0);
#pragma unroll
            for (int nt = 0; nt < 16; nt++) {
                uint32_t (*cur)[2] = (nt & 1) ? bf1 : bf0;
                uint32_t (*nxt)[2] = (nt & 1) ? bf0 : bf1;
                float d0 = 0, d1 = 0, d2 = 0, d3 = 0;
#pragma unroll
                for (int s = 0; s < 8; s++)
                    mma16816(d0, d1, d2, d3, ahi[s][0], ahi[s][1], ahi[s][2], ahi[s][3],
                             cur[s][0], cur[s][1]);
                if (nt < 15) LOAD_BF(nxt, nt + 1);
                float y0 = d0 * __expf(d0), y1 = d1 * __expf(d1);
                float y2 = d2 * __expf(d2), y3 = d3 * __expf(d3);
                mA = fmaxf(mA, fmaxf(d0, d1));
                mB = fmaxf(mB, fmaxf(d2, d3));
                TA += fabsf(y0) + fabsf(y1);
                TB += fabsf(y2) + fabsf(y3);
                __half2 p0 = __floats2half2_rn(y0, y1);
                __half2 p1 = __floats2half2_rn(y2, y3);
                int qb = nt * 16 + 4 * c4;           // byte within 256B row
                *(uint32_t*)(yrA + ((qb + rotA) & 255)) = *(uint32_t*)&p0;
                *(uint32_t*)(yrB + ((qb + rotB) & 255)) = *(uint32_t*)&p1;
            }
        }
        __syncthreads();   // MMA done reading X, y staged

        // refill X with qt+1 (overlaps copy-out below)
        if (qt < 3) {
            const uint4* gqn = (const uint4*)(g_qh + (size_t)(b * 4 + qt + 1) * 32768);
            for (int i = tid; i < 2048; i += 256) cp16(smb + X_OFF + i * 16, gqn + i);
            CP_COMMIT();
        }
        // copy y staging -> g_xe (streaming stores)
        for (int idx = tid; idx < 2048; idx += 256) {
            int uu = idx >> 4, c = idx & 15;
            uint4 v = *(const uint4*)(sm + A_OFF + uu * 256 + ((c * 16 + uu * 16) & 255));
            __stcs(&dst[uu * 64 + qt * 16 + c], v);
        }
        if (qt < 3) CP_WAIT(0);
        __syncthreads();
    }

    // reduce stats over the 4 lanes of each quad
    mA = fmaxf(mA, __shfl_xor_sync(0xFFFFFFFFu, mA, 1));
    mA = fmaxf(mA, __shfl_xor_sync(0xFFFFFFFFu, mA, 2));
    TA += __shfl_xor_sync(0xFFFFFFFFu, TA, 1);
    TA += __shfl_xor_sync(0xFFFFFFFFu, TA, 2);
    mB = fmaxf(mB, __shfl_xor_sync(0xFFFFFFFFu, mB, 1));
    mB = fmaxf(mB, __shfl_xor_sync(0xFFFFFFFFu, mB, 2));
    TB += __shfl_xor_sync(0xFFFFFFFFu, TB, 1);
    TB += __shfl_xor_sync(0xFFFFFFFFu, TB, 2);

    float* smm = (float*)(sm + STAT_OFF);
    float* smt = smm + 128;
    if (c4 == 0) {
        smm[u0 + r4] = mA;      smt[u0 + r4] = TA;
        smm[u0 + 8 + r4] = mB;  smt[u0 + 8 + r4] = TB;
    }
    __syncthreads();

    if (tid < 128) {
        float m = smm[tid], T = smt[tid];
        float vu = g_v[((size_t)b * KK + kidx) * TT + tid];
        g_w[((size_t)b * KK + kidx) * TT + tid] = vu / (T + __expf(m));
    }
}

// ---------------- pass 2: partial out over k-chunk of 32; 16 replicas ----------------
// grid: (64, BB*NREP), block 128 -> 8192 threads per (b,kc) slice
__global__ __launch_bounds__(128) void pass2() {
    __shared__ float ws[32 * 2];                 // w[k][u_local] for this CTA
    int bykc = blockIdx.y;                       // b*16 + kc
    int b = bykc >> 4, kc = bykc & 15;
    int s = blockIdx.x * 128 + threadIdx.x;      // 8192 per slice
    int qg = s & 63, u = s >> 6;                 // u in [0,128)
    int ubase = (blockIdx.x * 128) >> 6;         // 2 u values per CTA
    if (threadIdx.x < 64) {
        int kk = threadIdx.x >> 1, ul = threadIdx.x & 1;
        ws[kk * 2 + ul] = g_w[((size_t)b * KK + kc * 32 + kk) * TT + ubase + ul];
    }
    __syncthreads();
    int ul = u - ubase;
    const uint4* src = (const uint4*)(g_xe + ((size_t)(b * KK + kc * 32) * TT + u) * QQ) + qg;
    const size_t kstride = (size_t)TT * QQ / 8;  // uint4 step per k
    float acc[8];
#pragma unroll
    for (int j = 0; j < 8; j++) acc[j] = 0.0f;
#pragma unroll 8
    for (int k = 0; k < 32; k++) {
        uint4 yv = __ldcs(&src[(size_t)k * kstride]);
        float wv = ws[k * 2 + ul];
        float2 f0 = __half22float2(*(__half2*)&yv.x);
        float2 f1 = __half22float2(*(__half2*)&yv.y);
        float2 f2 = __half22float2(*(__half2*)&yv.z);
        float2 f3 = __half22float2(*(__half2*)&yv.w);
        acc[0] = fmaf(wv, f0.x, acc[0]); acc[1] = fmaf(wv, f0.y, acc[1]);
        acc[2] = fmaf(wv, f1.x, acc[2]); acc[3] = fmaf(wv, f1.y, acc[3]);
        acc[4] = fmaf(wv, f2.x, acc[4]); acc[5] = fmaf(wv, f2.y, acc[5]);
        acc[6] = fmaf(wv, f3.x, acc[6]); acc[7] = fmaf(wv, f3.y, acc[7]);
    }
    float* dstp = g_accr + (size_t)kc * BB * QQ * TT;
    int q0 = qg * 8;
#pragma unroll
    for (int j = 0; j < 8; j++)
        dstp[((size_t)b * QQ + q0 + j) * TT + u] = acc[j];
}

// ---------------- launch ----------------
extern "C" void kernel_launch(void* const* d_in, const int* in_sizes, int n_in,
                              void* d_out, int out_size) {
    const float* q_in = (const float*)d_in[0];
    const float* k_in = (const float*)d_in[1];
    const float* v_in = (const float*)d_in[2];
    const float* Wk   = (const float*)d_in[3];
    const float* Wq   = (const float*)d_in[4];
    const float* Wv   = (const float*)d_in[5];
    const float* Wl   = (const float*)d_in[6];
    const float* Wo   = (const float*)d_in[7];
    float* out = (float*)d_out;

    const int SMEM_G = (128 * 132 + 32 * 132) * 4;   // 84480
    cudaFuncSetAttribute(gemm_out, cudaFuncAttributeMaxDynamicSharedMemorySize, SMEM_GO);
    cudaFuncSetAttribute(proj3,    cudaFuncAttributeMaxDynamicSharedMemorySize, SMEM_G);
    cudaFuncSetAttribute(pass1,    cudaFuncAttributeMaxDynamicSharedMemorySize, P1_SMEM);

    proj3<<<dim3(32, 3), 256, SMEM_G>>>(q_in, Wq, k_in, Wk, v_in, Wv);
    prep_images<<<BB * KK + 8, 256>>>(Wl);
    pass1<<<BB * KK, 256, P1_SMEM>>>();
    pass2<<<dim3(64, BB * NREP), 128>>>();
    gemm_out<<<64, 256, SMEM_GO>>>(Wo, out);
}

// round 17
// speedup vs baseline: 1.1548x; 1.0842x over previous
#include <cuda_runtime.h>
#include <cuda_fp16.h>
#include <cstdint>

#define BB 2
#define KK 512
#define QQ 512
#define TT 128
#define NREP 16

// ---------------- device scratch ----------------
__device__ float g_k[BB * KK * TT];
__device__ float g_q[BB * QQ * TT];
__device__ float g_v[BB * KK * TT];
__device__ float g_w[BB * KK * TT];                  // per (b,k,u) scale v_u/(T+e^m)
__device__ float g_accr[NREP * BB * QQ * TT];        // k-split partial sums
__device__ __half g_xe[(size_t)BB * KK * TT * QQ];   // 128MB unscaled y = x*e^x
__device__ unsigned char g_qh[BB * 4 * 32768];       // 256KB swizzled fp16 q tiles

// ---------------- helpers ----------------
__device__ __forceinline__ uint32_t smem_u32(const void* p) {
    uint32_t a;
    asm("{ .reg .u64 t; cvta.to.shared.u64 t, %1; cvt.u32.u64 %0, t; }" : "=r"(a) : "l"(p));
    return a;
}
__device__ __forceinline__ void ldsm_x4(uint32_t& r0, uint32_t& r1, uint32_t& r2, uint32_t& r3,
                                        uint32_t addr) {
    asm volatile("ldmatrix.sync.aligned.m8n8.x4.shared.b16 {%0,%1,%2,%3}, [%4];"
                 : "=r"(r0), "=r"(r1), "=r"(r2), "=r"(r3) : "r"(addr));
}
__device__ __forceinline__ void mma16816(float& d0, float& d1, float& d2, float& d3,
                                         uint32_t a0, uint32_t a1, uint32_t a2, uint32_t a3,
                                         uint32_t b0, uint32_t b1) {
    asm volatile("mma.sync.aligned.m16n8k16.row.col.f32.f16.f16.f32 "
                 "{%0,%1,%2,%3}, {%4,%5,%6,%7}, {%8,%9}, {%0,%1,%2,%3};"
                 : "+f"(d0), "+f"(d1), "+f"(d2), "+f"(d3)
                 : "r"(a0), "r"(a1), "r"(a2), "r"(a3), "r"(b0), "r"(b1));
}
__device__ __forceinline__ void cp16(uint32_t smem, const void* g) {
    asm volatile("cp.async.cg.shared.global [%0], [%1], 16;" :: "r"(smem), "l"(g));
}
#define CP_COMMIT() asm volatile("cp.async.commit_group;" ::: "memory")
#define CP_WAIT(N)  asm volatile("cp.async.wait_group %0;" :: "n"(N) : "memory")

// smem byte layout for pass1 (total 66560 -> 3 CTAs/SM)
#define A_OFF    0          // 32KB: A_k image; reused as y staging after frag load
#define X_OFF    32768      // 32KB X buffer (single)
#define STAT_OFF 65536      // kraw (prolog) / m[128],T[128] (epilog) = 1KB
#define P1_SMEM  66560

// ---------------- prep: build swizzled fp16 q tiles (8 blocks) ----------------
__global__ __launch_bounds__(256) void prep_images() {
    int i = blockIdx.x;                   // 0..7: b = i>>2, qt = i&3
    int tid = threadIdx.x;
    int r = tid >> 1, h = tid & 1;
    int r7 = r & 7;
    int b = i >> 2, qt = i & 3;
    const float4* qrow = (const float4*)(g_q + ((size_t)b * QQ + qt * 128 + r) * TT + h * 64);
    unsigned char* xrow = g_qh + (size_t)i * 32768 + r * 256;
#pragma unroll
    for (int c8 = 0; c8 < 8; c8++) {
        float4 qa = qrow[c8 * 2], qb = qrow[c8 * 2 + 1];
        __half2 h0 = __floats2half2_rn(qa.x, qa.y);
        __half2 h1 = __floats2half2_rn(qa.z, qa.w);
        __half2 h2 = __floats2half2_rn(qb.x, qb.y);
        __half2 h3 = __floats2half2_rn(qb.z, qb.w);
        int chunk = h * 8 + c8;
        uint4 pk;
        pk.x = *(uint32_t*)&h0; pk.y = *(uint32_t*)&h1;
        pk.z = *(uint32_t*)&h2; pk.w = *(uint32_t*)&h3;
        *(uint4*)(xrow + ((chunk ^ r7) << 4)) = pk;
    }
}

// ---------------- fp32 GEMM 32-row tiles: out[r,u] = sum_t in[r,t]*W[u,t] ----------------
__device__ __forceinline__ void gemm32_body(const float* __restrict__ in,
                                            const float* __restrict__ W,
                                            float* __restrict__ out, int r0) {
    extern __shared__ float smf[];
    float* sW = smf;                 // [128][132]
    float* sI = smf + 128 * 132;     // [32][132]
    int tid = threadIdx.x;
    for (int i = tid; i < 128 * 128; i += 256) { int u = i >> 7, t = i & 127; sW[u * 132 + t] = W[i]; }
    for (int i = tid; i < 32 * 128;  i += 256) {
        int r = i >> 7, t = i & 127;
        sI[r * 132 + t] = in[(size_t)r0 * 128 + i];
    }
    __syncthreads();
    int tx = tid & 15, ty = tid >> 4;
    float acc[2][8];
#pragma unroll
    for (int i = 0; i < 2; i++)
#pragma unroll
        for (int j = 0; j < 8; j++) acc[i][j] = 0.0f;
    for (int t = 0; t < 128; t += 4) {
        float4 a0 = *(const float4*)&sI[(ty * 2 + 0) * 132 + t];
        float4 a1 = *(const float4*)&sI[(ty * 2 + 1) * 132 + t];
#pragma unroll
        for (int j = 0; j < 8; j++) {
            float4 bv = *(const float4*)&sW[(tx + 16 * j) * 132 + t];
            acc[0][j] = fmaf(a0.x, bv.x, acc[0][j]); acc[0][j] = fmaf(a0.y, bv.y, acc[0][j]);
            acc[0][j] = fmaf(a0.z, bv.z, acc[0][j]); acc[0][j] = fmaf(a0.w, bv.w, acc[0][j]);
            acc[1][j] = fmaf(a1.x, bv.x, acc[1][j]); acc[1][j] = fmaf(a1.y, bv.y, acc[1][j]);
            acc[1][j] = fmaf(a1.z, bv.z, acc[1][j]); acc[1][j] = fmaf(a1.w, bv.w, acc[1][j]);
        }
    }
#pragma unroll
    for (int i = 0; i < 2; i++)
#pragma unroll
        for (int j = 0; j < 8; j++)
            out[(size_t)(r0 + ty * 2 + i) * 128 + tx + 16 * j] = acc[i][j];
}

// ---------------- gemm_out: 16-row tiles, folds NREP replica sum ----------------
#define SMEM_GO ((128 * 132 + 16 * 132) * 4)
__global__ __launch_bounds__(256) void gemm_out(const float* __restrict__ W,
                                                float* __restrict__ out) {
    extern __shared__ float smf[];
    float* sW = smf;                 // [128][132]
    float* sI = smf + 128 * 132;     // [16][132]
    int tid = threadIdx.x;
    int r0 = blockIdx.x * 16;
    for (int i = tid; i < 128 * 128; i += 256) { int u = i >> 7, t = i & 127; sW[u * 132 + t] = W[i]; }
    for (int i = tid; i < 16 * 128; i += 256) {
        int r = i >> 7, t = i & 127;
        const size_t off = (size_t)r0 * 128 + i;
        const size_t st = (size_t)BB * QQ * TT;
        float v = 0.0f;
#pragma unroll
        for (int rr = 0; rr < NREP; rr++) v += g_accr[off + (size_t)rr * st];
        sI[r * 132 + t] = v;
    }
    __syncthreads();
    int tx = tid & 15, ty = tid >> 4;   // r = r0+ty, u = tx + 16*j
    float acc[8];
#pragma unroll
    for (int j = 0; j < 8; j++) acc[j] = 0.0f;
    for (int t = 0; t < 128; t += 4) {
        float4 a0 = *(const float4*)&sI[ty * 132 + t];
#pragma unroll
        for (int j = 0; j < 8; j++) {
            float4 bv = *(const float4*)&sW[(tx + 16 * j) * 132 + t];
            acc[j] = fmaf(a0.x, bv.x, acc[j]); acc[j] = fmaf(a0.y, bv.y, acc[j]);
            acc[j] = fmaf(a0.z, bv.z, acc[j]); acc[j] = fmaf(a0.w, bv.w, acc[j]);
        }
    }
#pragma unroll
    for (int j = 0; j < 8; j++)
        out[(size_t)(r0 + ty) * 128 + tx + 16 * j] = acc[j];
}

__global__ __launch_bounds__(256) void proj3(const float* __restrict__ qi, const float* __restrict__ Wq,
                                             const float* __restrict__ ki, const float* __restrict__ Wk,
                                             const float* __restrict__ vi, const float* __restrict__ Wv) {
    int r0 = blockIdx.x * 32;
    if (blockIdx.y == 0)      gemm32_body(qi, Wq, g_q, r0);
    else if (blockIdx.y == 1) gemm32_body(ki, Wk, g_k, r0);
    else                      gemm32_body(vi, Wv, g_v, r0);
}

// load B-fragments for one nt row-block
#define LOAD_BF(dst, ntv)                                                      \
    do {                                                                       \
        int row_ = (ntv) * 8 + brow7;                                          \
        uint32_t rb_ = xb + row_ * 256;                                        \
        int r7_ = row_ & 7;                                                    \
        _Pragma("unroll")                                                      \
        for (int sp = 0; sp < 4; sp++) {                                       \
            int chunk_ = 4 * sp + bgrp;                                        \
            uint32_t t0_, t1_, t2_, t3_;                                       \
            ldsm_x4(t0_, t1_, t2_, t3_, rb_ + ((chunk_ ^ r7_) << 4));          \
            dst[2 * sp][0] = t0_; dst[2 * sp][1] = t1_;                        \
            dst[2 * sp + 1][0] = t2_; dst[2 * sp + 1][1] = t3_;                \
        }                                                                      \
    } while (0)

// ---------------- pass 1: CTA per (b,k); 3 CTAs/SM; in-CTA A build ----------------
__global__ __launch_bounds__(256, 3) void pass1(const float* __restrict__ Wl) {
    extern __shared__ unsigned char sm[];
    int tid = threadIdx.x, wid = tid >> 5, lane = tid & 31;
    int b = blockIdx.x >> 9, kidx = blockIdx.x & 511;
    uint32_t smb = smem_u32(sm);

    // X0 async load (overlaps A build below)
    {
        const uint4* gq0 = (const uint4*)(g_qh + (size_t)(b * 4 + 0) * 32768);
        for (int i = tid; i < 2048; i += 256) cp16(smb + X_OFF + i * 16, gq0 + i);
        CP_COMMIT();
    }
    // k row -> smem scratch (STAT area; dead until epilogue)
    float* kraw = (float*)(sm + STAT_OFF);
    if (tid < 32)
        ((float4*)kraw)[tid] = ((const float4*)(g_k + ((size_t)b * KK + kidx) * TT))[tid];
    __syncthreads();

    // build A image fp16(Wl*k), swizzled, into A_OFF (identical numerics to old prep)
    {
        int r = tid >> 1, h = tid & 1, r7 = r & 7;
        const float4* wrow = (const float4*)(Wl + (size_t)r * TT + h * 64);
        const float4* krow = (const float4*)(kraw + h * 64);
        unsigned char* arow = sm + A_OFF + r * 256;
#pragma unroll
        for (int c8 = 0; c8 < 8; c8++) {
            float4 qa = wrow[c8 * 2], qb = wrow[c8 * 2 + 1];
            float4 ka = krow[c8 * 2], kb = krow[c8 * 2 + 1];
            __half2 h0 = __floats2half2_rn(qa.x * ka.x, qa.y * ka.y);
            __half2 h1 = __floats2half2_rn(qa.z * ka.z, qa.w * ka.w);
            __half2 h2 = __floats2half2_rn(qb.x * kb.x, qb.y * kb.y);
            __half2 h3 = __floats2half2_rn(qb.z * kb.z, qb.w * kb.w);
            int chunk = h * 8 + c8;
            uint4 pk;
            pk.x = *(uint32_t*)&h0; pk.y = *(uint32_t*)&h1;
            pk.z = *(uint32_t*)&h2; pk.w = *(uint32_t*)&h3;
            *(uint4*)(arow + ((chunk ^ r7) << 4)) = pk;
        }
    }
    __syncthreads();

    // A fragments: warp wid owns u-rows [wid*16, +16), K=128 (8 k-steps)
    int u0 = wid * 16;
    uint32_t ahi[8][4];
    {
        int row = u0 + (lane & 7) + ((lane >> 3) & 1) * 8;
        int cpar = (lane >> 4) & 1;
        int r7 = lane & 7;
        uint32_t rbh = smb + A_OFF + row * 256;
#pragma unroll
        for (int s = 0; s < 8; s++) {
            int chunk = 2 * s + cpar;
            ldsm_x4(ahi[s][0], ahi[s][1], ahi[s][2], ahi[s][3], rbh + ((chunk ^ r7) << 4));
        }
    }
    CP_WAIT(0);
    __syncthreads();   // X visible; A region now free for y staging

    int r4 = lane >> 2, c4 = lane & 3;
    float mA = -1e30f, TA = 0.0f, mB = -1e30f, TB = 0.0f;
    uint4* dst = (uint4*)(g_xe + ((size_t)(b * KK + kidx) * TT) * QQ);
    uint32_t xb = smb + X_OFF;

    for (int qt = 0; qt < 4; qt++) {
        // pipelined MMA + exp epilogue + inline flush to A region
        {
            int brow7 = lane & 7;
            int bgrp = lane >> 3;         // 0..3
            int uA = u0 + r4, uB = u0 + 8 + r4;
            unsigned char* yrA = sm + A_OFF + uA * 256;
            unsigned char* yrB = sm + A_OFF + uB * 256;
            int rotA = uA * 16, rotB = uB * 16;
            uint32_t bf0[8][2], bf1[8][2];
            LOAD_BF(bf0, 0);
#pragma unroll
            for (int nt = 0; nt < 16; nt++) {
                uint32_t (*cur)[2] = (nt & 1) ? bf1 : bf0;
                uint32_t (*nxt)[2] = (nt & 1) ? bf0 : bf1;
                float d0 = 0, d1 = 0, d2 = 0, d3 = 0;
#pragma unroll
                for (int s = 0; s < 8; s++)
                    mma16816(d0, d1, d2, d3, ahi[s][0], ahi[s][1], ahi[s][2], ahi[s][3],
                             cur[s][0], cur[s][1]);
                if (nt < 15) LOAD_BF(nxt, nt + 1);
                float y0 = d0 * __expf(d0), y1 = d1 * __expf(d1);
                float y2 = d2 * __expf(d2), y3 = d3 * __expf(d3);
                mA = fmaxf(mA, fmaxf(d0, d1));
                mB = fmaxf(mB, fmaxf(d2, d3));
                TA += fabsf(y0) + fabsf(y1);
                TB += fabsf(y2) + fabsf(y3);
                __half2 p0 = __floats2half2_rn(y0, y1);
                __half2 p1 = __floats2half2_rn(y2, y3);
                int qb = nt * 16 + 4 * c4;           // byte within 256B row
                *(uint32_t*)(yrA + ((qb + rotA) & 255)) = *(uint32_t*)&p0;
                *(uint32_t*)(yrB + ((qb + rotB) & 255)) = *(uint32_t*)&p1;
            }
        }
        __syncthreads();   // MMA done reading X, y staged

        // refill X with qt+1 (overlaps copy-out below)
        if (qt < 3) {
            const uint4* gqn = (const uint4*)(g_qh + (size_t)(b * 4 + qt + 1) * 32768);
            for (int i = tid; i < 2048; i += 256) cp16(smb + X_OFF + i * 16, gqn + i);
            CP_COMMIT();
        }
        // copy y staging -> g_xe (streaming stores)
        for (int idx = tid; idx < 2048; idx += 256) {
            int uu = idx >> 4, c = idx & 15;
            uint4 v = *(const uint4*)(sm + A_OFF + uu * 256 + ((c * 16 + uu * 16) & 255));
            __stcs(&dst[uu * 64 + qt * 16 + c], v);
        }
        if (qt < 3) CP_WAIT(0);
        __syncthreads();
    }

    // reduce stats over the 4 lanes of each quad
    mA = fmaxf(mA, __shfl_xor_sync(0xFFFFFFFFu, mA, 1));
    mA = fmaxf(mA, __shfl_xor_sync(0xFFFFFFFFu, mA, 2));
    TA += __shfl_xor_sync(0xFFFFFFFFu, TA, 1);
    TA += __shfl_xor_sync(0xFFFFFFFFu, TA, 2);
    mB = fmaxf(mB, __shfl_xor_sync(0xFFFFFFFFu, mB, 1));
    mB = fmaxf(mB, __shfl_xor_sync(0xFFFFFFFFu, mB, 2));
    TB += __shfl_xor_sync(0xFFFFFFFFu, TB, 1);
    TB += __shfl_xor_sync(0xFFFFFFFFu, TB, 2);

    float* smm = (float*)(sm + STAT_OFF);
    float* smt = smm + 128;
    if (c4 == 0) {
        smm[u0 + r4] = mA;      smt[u0 + r4] = TA;
        smm[u0 + 8 + r4] = mB;  smt[u0 + 8 + r4] = TB;
    }
    __syncthreads();

    if (tid < 128) {
        float m = smm[tid], T = smt[tid];
        float vu = g_v[((size_t)b * KK + kidx) * TT + tid];
        g_w[((size_t)b * KK + kidx) * TT + tid] = vu / (T + __expf(m));
    }
}

// ---------------- pass 2: partial out over k-chunk of 32; 16 replicas ----------------
// grid: (64, BB*NREP), block 128 -> 8192 threads per (b,kc) slice
__global__ __launch_bounds__(128) void pass2() {
    __shared__ float ws[32 * 2];                 // w[k][u_local] for this CTA
    int bykc = blockIdx.y;                       // b*16 + kc
    int b = bykc >> 4, kc = bykc & 15;
    int s = blockIdx.x * 128 + threadIdx.x;      // 8192 per slice
    int qg = s & 63, u = s >> 6;                 // u in [0,128)
    int ubase = (blockIdx.x * 128) >> 6;         // 2 u values per CTA
    if (threadIdx.x < 64) {
        int kk = threadIdx.x >> 1, ul = threadIdx.x & 1;
        ws[kk * 2 + ul] = g_w[((size_t)b * KK + kc * 32 + kk) * TT + ubase + ul];
    }
    __syncthreads();
    int ul = u - ubase;
    const uint4* src = (const uint4*)(g_xe + ((size_t)(b * KK + kc * 32) * TT + u) * QQ) + qg;
    const size_t kstride = (size_t)TT * QQ / 8;  // uint4 step per k
    float acc[8];
#pragma unroll
    for (int j = 0; j < 8; j++) acc[j] = 0.0f;
#pragma unroll 8
    for (int k = 0; k < 32; k++) {
        uint4 yv = __ldcs(&src[(size_t)k * kstride]);
        float wv = ws[k * 2 + ul];
        float2 f0 = __half22float2(*(__half2*)&yv.x);
        float2 f1 = __half22float2(*(__half2*)&yv.y);
        float2 f2 = __half22float2(*(__half2*)&yv.z);
        float2 f3 = __half22float2(*(__half2*)&yv.w);
        acc[0] = fmaf(wv, f0.x, acc[0]); acc[1] = fmaf(wv, f0.y, acc[1]);
        acc[2] = fmaf(wv, f1.x, acc[2]); acc[3] = fmaf(wv, f1.y, acc[3]);
        acc[4] = fmaf(wv, f2.x, acc[4]); acc[5] = fmaf(wv, f2.y, acc[5]);
        acc[6] = fmaf(wv, f3.x, acc[6]); acc[7] = fmaf(wv, f3.y, acc[7]);
    }
    float* dstp = g_accr + (size_t)kc * BB * QQ * TT;
    int q0 = qg * 8;
#pragma unroll
    for (int j = 0; j < 8; j++)
        dstp[((size_t)b * QQ + q0 + j) * TT + u] = acc[j];
}

// ---------------- launch ----------------
extern "C" void kernel_launch(void* const* d_in, const int* in_sizes, int n_in,
                              void* d_out, int out_size) {
    const float* q_in = (const float*)d_in[0];
    const float* k_in = (const float*)d_in[1];
    const float* v_in = (const float*)d_in[2];
    const float* Wk   = (const float*)d_in[3];
    const float* Wq   = (const float*)d_in[4];
    const float* Wv   = (const float*)d_in[5];
    const float* Wl   = (const float*)d_in[6];
    const float* Wo   = (const float*)d_in[7];
    float* out = (float*)d_out;

    const int SMEM_G = (128 * 132 + 32 * 132) * 4;   // 84480
    cudaFuncSetAttribute(gemm_out, cudaFuncAttributeMaxDynamicSharedMemorySize, SMEM_GO);
    cudaFuncSetAttribute(proj3,    cudaFuncAttributeMaxDynamicSharedMemorySize, SMEM_G);
    cudaFuncSetAttribute(pass1,    cudaFuncAttributeMaxDynamicSharedMemorySize, P1_SMEM);

    proj3<<<dim3(32, 3), 256, SMEM_G>>>(q_in, Wq, k_in, Wk, v_in, Wv);
    prep_images<<<8, 256>>>();
    pass1<<<BB * KK, 256, P1_SMEM>>>(Wl);
    pass2<<<dim3(64, BB * NREP), 128>>>();
    gemm_out<<<64, 256, SMEM_GO>>>(Wo, out);
}